// round 7
// baseline (speedup 1.0000x reference)
#include <cuda_runtime.h>
#include <stdint.h>

// kNN: B=2, N=2048, D=16, K=16. Output (B,N,K,2) FLOAT32: [b, idx].
//
// transpose_kernel: AoS points -> SoA float4 scratch (coalesced loads).
// knn_kernel: ONE WARP PER QUERY (32-thread CTAs).
//   Pass 1 (branch-free): lane computes keys (bits of sqrt distance, self=INF)
//     for its 64 candidates j = t*32+lane, caches them in padded SMEM [64][33]
//     (conflict-free writes AND conflict-free winner-column reads), tracks its
//     running (min-key, step).
//   Pops: 16 rounds. Warp-min over lane mins via 64-bit (key<<32 | j) shfl
//     reduce -> exact jax.lax.top_k order (ascending dist, ties -> lower idx).
//     Winner's popped entry set to INF in SMEM; warp cooperatively re-mins the
//     winner's cached column (2 LDS/lane + shfl reduce). Exhaustive => exact.

#define NPTS 2048
#define KNN  16

__device__ float4 T4g[2][4][NPTS];   // 256 KB static scratch

__global__ void transpose_kernel(const float* __restrict__ points)
{
    int idx = blockIdx.x * blockDim.x + threadIdx.x;   // b*8192 + c*2048 + j
    if (idx >= 2 * 4 * NPTS) return;
    int j = idx & (NPTS - 1);
    int c = (idx >> 11) & 3;
    int b = idx >> 13;
    const float4* P4 = reinterpret_cast<const float4*>(points);
    T4g[b][c][j] = P4[(b * NPTS + j) * 4 + c];
}

__device__ __forceinline__ unsigned long long umin64(unsigned long long a,
                                                     unsigned long long b)
{
    return (b < a) ? b : a;
}

__global__ void knn_kernel(float2* __restrict__ out)
{
    __shared__ unsigned smK[64][33];          // [t][lane], pad 33 => winner
                                              // column reads conflict-free
    const int b    = blockIdx.y;
    const int lane = threadIdx.x;             // 32-thread CTA == one warp
    const int q    = blockIdx.x;              // 0..2047

    const float4 q0 = T4g[b][0][q];
    const float4 q1 = T4g[b][1][q];
    const float4 q2 = T4g[b][2][q];
    const float4 q3 = T4g[b][3][q];

    unsigned mk = 0xFFFFFFFFu;                // lane running min key
    int      mt = 0;                          // its step

    // ---- Pass 1: compute + cache all keys, branch-free ----
#pragma unroll 2
    for (int t = 0; t < NPTS / 32; ++t) {
        const int j = t * 32 + lane;
        float4 a0 = T4g[b][0][j];
        float4 a1 = T4g[b][1][j];
        float4 a2 = T4g[b][2][j];
        float4 a3 = T4g[b][3][j];

        // Sequential c=0..15 accumulation (bit-matches reference; proven).
        float s = 0.0f, d;
        d = q0.x - a0.x; s = fmaf(d, d, s);
        d = q0.y - a0.y; s = fmaf(d, d, s);
        d = q0.z - a0.z; s = fmaf(d, d, s);
        d = q0.w - a0.w; s = fmaf(d, d, s);
        d = q1.x - a1.x; s = fmaf(d, d, s);
        d = q1.y - a1.y; s = fmaf(d, d, s);
        d = q1.z - a1.z; s = fmaf(d, d, s);
        d = q1.w - a1.w; s = fmaf(d, d, s);
        d = q2.x - a2.x; s = fmaf(d, d, s);
        d = q2.y - a2.y; s = fmaf(d, d, s);
        d = q2.z - a2.z; s = fmaf(d, d, s);
        d = q2.w - a2.w; s = fmaf(d, d, s);
        d = q3.x - a3.x; s = fmaf(d, d, s);
        d = q3.y - a3.y; s = fmaf(d, d, s);
        d = q3.z - a3.z; s = fmaf(d, d, s);
        d = q3.w - a3.w; s = fmaf(d, d, s);

        unsigned key = __float_as_uint(__fsqrt_rn(s));  // compare post-sqrt
        if (j == q) key = 0xFFFFFFFFu;                  // exclude self

        smK[t][lane] = key;
        if (key < mk) { mk = key; mt = t; }             // strict < : earlier j
    }
    __syncwarp();

    // ---- Pops: 16 exact extractions ----
    float2* outp = out + ((size_t)b * NPTS + q) * KNN;
    const float fb = (float)b;

#pragma unroll 1
    for (int r = 0; r < KNN; ++r) {
        // Global min over lanes: 64-bit (key << 32 | j), unique j => unique key.
        unsigned long long P =
            ((unsigned long long)mk << 32) | (unsigned)(mt * 32 + lane);
        unsigned long long V = P;
#pragma unroll
        for (int off = 16; off > 0; off >>= 1)
            V = umin64(V, __shfl_xor_sync(0xFFFFFFFFu, V, off));

        const unsigned wj = (unsigned)V;        // winning global index
        if (lane == 0)
            outp[r] = make_float2(fb, (float)(int)wj);

        const int wl = wj & 31;                 // winner lane
        const int wt = wj >> 5;                 // winner step

        // Remove popped entry, then re-min the winner's cached column.
        if (lane == 0) smK[wt][wl] = 0xFFFFFFFFu;
        __syncwarp();

        unsigned k1 = smK[lane][wl];
        unsigned k2 = smK[lane + 32][wl];
        unsigned long long p1 =
            ((unsigned long long)k1 << 32) | (unsigned)(lane * 32 + wl);
        unsigned long long p2 =
            ((unsigned long long)k2 << 32) | (unsigned)((lane + 32) * 32 + wl);
        unsigned long long W = umin64(p1, p2);
#pragma unroll
        for (int off = 16; off > 0; off >>= 1)
            W = umin64(W, __shfl_xor_sync(0xFFFFFFFFu, W, off));

        if (lane == wl) {
            mk = (unsigned)(W >> 32);
            mt = (int)(((unsigned)W) >> 5);
        }
        __syncwarp();   // order this pop's LDS before next pop's STS
    }
}

extern "C" void kernel_launch(void* const* d_in, const int* in_sizes, int n_in,
                              void* d_out, int out_size)
{
    // points (2*2048*16) is the SMALLER input (features is 4x larger).
    const float* points;
    if (n_in >= 2) {
        points = (in_sizes[0] <= in_sizes[1]) ? (const float*)d_in[0]
                                              : (const float*)d_in[1];
    } else {
        points = (const float*)d_in[0];
    }

    transpose_kernel<<<(2 * 4 * NPTS + 255) / 256, 256>>>(points);

    dim3 grid(NPTS, 2);                 // 4096 CTAs x 32 threads = warp/query
    knn_kernel<<<grid, 32>>>((float2*)d_out);
}